// round 13
// baseline (speedup 1.0000x reference)
#include <cuda_runtime.h>
#include <cuda_bf16.h>

// ROI bilinear pooling (TF2 half_pixel_centers resize semantics).
// img: [1, 100, 100, 512] f32 NHWC ; rois: [1, 300, 4] int32 (x, y, w, h)
// out: [1, 300, 14, 14, 512] f32
//
// R12: ALL-32-BIT memory accesses. Any multi-wavefront LDG pays the ~2.07
// cyc/wf within-instruction replay rate (measured: 128b and 64b variants both
// land ~35-37us = 80wf/px * 2.07). LDG.32 at warp-contiguous addresses is
// exactly ONE 128B wavefront per instruction, streaming cross-instruction at
// ~1.0 cyc/wf; the binder shifts to the LSU accept floor (1.82 cyc/instr *
// 80 instr/px ~= 30.5us). 512 threads/block = one channel per thread; block
// per (roi, py); 4x LDG.32 + 4 FFMA + 1 STG.32 per px. Coord precompute in
// smem (threads 0..13, one barrier). launch_bounds(512,4) => 64 warps/SM.

#define POOL 14
#define NUM_ROIS 300
#define FM_H 100
#define FM_W 100
#define FM_C 512
#define NUM_ITEMS (NUM_ROIS * POOL)   // 4200

__global__ __launch_bounds__(512, 4)
void roi_pool_kernel(const float* __restrict__ img,
                     const int*   __restrict__ rois,
                     float*       __restrict__ out)
{
    __shared__ int4   s_off[POOL];   // float-element offsets of the 4 gather rows
    __shared__ float4 s_w[POOL];     // bilinear weights w00,w01,w10,w11

    const int t    = threadIdx.x;    // 0..511 : one channel
    const int item = blockIdx.x;     // 0..4199 = (roi, py)

    if (t < POOL) {
        const int px = t;
        const int r  = item / POOL;
        const int py = item - r * POOL;

        const int4 roi = __ldg(((const int4*)rois) + r);
        const int rx = roi.x, ry = roi.y, rw = roi.z, rh = roi.w;

        // y axis (half-pixel centers)
        const float srcy = (py + 0.5f) * ((float)rh * (1.0f / POOL)) - 0.5f;
        const float fy   = floorf(srcy);
        const float ty   = srcy - fy;
        const int   fyi  = (int)fy;
        const int   ylo  = min(max(fyi,     0), rh - 1) + ry;
        const int   yhi  = min(max(fyi + 1, 0), rh - 1) + ry;

        // x axis
        const float srcx = (px + 0.5f) * ((float)rw * (1.0f / POOL)) - 0.5f;
        const float fx   = floorf(srcx);
        const float tx   = srcx - fx;
        const int   fxi  = (int)fx;
        const int   xlo  = min(max(fxi,     0), rw - 1) + rx;
        const int   xhi  = min(max(fxi + 1, 0), rw - 1) + rx;

        const int rowlo = ylo * (FM_W * FM_C);   // float index of row start
        const int rowhi = yhi * (FM_W * FM_C);

        int4 off;
        off.x = rowlo + xlo * FM_C;   // (ylo, xlo)
        off.y = rowlo + xhi * FM_C;   // (ylo, xhi)
        off.z = rowhi + xlo * FM_C;   // (yhi, xlo)
        off.w = rowhi + xhi * FM_C;   // (yhi, xhi)
        s_off[px] = off;

        const float wy0 = 1.0f - ty, wy1 = ty;
        const float wx0 = 1.0f - tx, wx1 = tx;
        float4 w;
        w.x = wy0 * wx0;
        w.y = wy0 * wx1;
        w.z = wy1 * wx0;
        w.w = wy1 * wx1;
        s_w[px] = w;
    }
    __syncthreads();

    float* optr = out + (size_t)item * (POOL * FM_C) + t;

    #pragma unroll 1
    for (int px = 0; px < POOL; ++px) {
        const int4   off = s_off[px];   // broadcast LDS.128
        const float4 w   = s_w[px];     // broadcast LDS.128

        const float a  = __ldg(img + off.x + t);   // LDG.32: one 128B wavefront
        const float bq = __ldg(img + off.y + t);
        const float c  = __ldg(img + off.z + t);
        const float d  = __ldg(img + off.w + t);

        const float o = w.x * a + w.y * bq + w.z * c + w.w * d;

        __stcs(optr + px * FM_C, o);   // STG.32, streaming
    }
}

extern "C" void kernel_launch(void* const* d_in, const int* in_sizes, int n_in,
                              void* d_out, int out_size)
{
    // Resolve inputs by size, not position: img = 5,120,000 elems; rois = 1,200.
    const float* img;
    const int*   rois;
    if (in_sizes[0] > in_sizes[1]) {
        img  = (const float*)d_in[0];
        rois = (const int*)d_in[1];
    } else {
        img  = (const float*)d_in[1];
        rois = (const int*)d_in[0];
    }
    float* out = (float*)d_out;

    roi_pool_kernel<<<NUM_ITEMS, 512>>>(img, rois, out);
}

// round 14
// speedup vs baseline: 1.0936x; 1.0936x over previous
#include <cuda_runtime.h>
#include <cuda_bf16.h>

// ROI bilinear pooling (TF2 half_pixel_centers resize semantics).
// img: [1, 100, 100, 512] f32 NHWC ; rois: [1, 300, 4] int32 (x, y, w, h)
// out: [1, 300, 14, 14, 512] f32
//
// R13: issue-lean ALL-32-BIT variant. R12 showed 32-bit accesses drown in
// auxiliary instructions (issue 72%, alu 63%) before the LSU floor (80 mem
// instr/px * 1.82cyc = ~30.4us) can bind. This version keeps the 512-thread /
// block-per-(roi,py) / smem-coord structure but: unroll-2 px loop, single
// IMAD.WIDE per gather address (base_t = img + t hoisted), store via
// [base + imm]. Target <=16 issued instrs per warp-px so the LSU floor binds.

#define POOL 14
#define NUM_ROIS 300
#define FM_H 100
#define FM_W 100
#define FM_C 512
#define NUM_ITEMS (NUM_ROIS * POOL)   // 4200

__global__ __launch_bounds__(512, 4)
void roi_pool_kernel(const float* __restrict__ img,
                     const int*   __restrict__ rois,
                     float*       __restrict__ out)
{
    __shared__ int4   s_off[POOL];   // float-element offsets of the 4 gather rows
    __shared__ float4 s_w[POOL];     // bilinear weights w00,w01,w10,w11

    const int t    = threadIdx.x;    // 0..511 : one channel
    const int item = blockIdx.x;     // 0..4199 = (roi, py)

    if (t < POOL) {
        const int px = t;
        const int r  = item / POOL;
        const int py = item - r * POOL;

        const int4 roi = __ldg(((const int4*)rois) + r);
        const int rx = roi.x, ry = roi.y, rw = roi.z, rh = roi.w;

        // y axis (half-pixel centers)
        const float srcy = (py + 0.5f) * ((float)rh * (1.0f / POOL)) - 0.5f;
        const float fy   = floorf(srcy);
        const float ty   = srcy - fy;
        const int   fyi  = (int)fy;
        const int   ylo  = min(max(fyi,     0), rh - 1) + ry;
        const int   yhi  = min(max(fyi + 1, 0), rh - 1) + ry;

        // x axis
        const float srcx = (px + 0.5f) * ((float)rw * (1.0f / POOL)) - 0.5f;
        const float fx   = floorf(srcx);
        const float tx   = srcx - fx;
        const int   fxi  = (int)fx;
        const int   xlo  = min(max(fxi,     0), rw - 1) + rx;
        const int   xhi  = min(max(fxi + 1, 0), rw - 1) + rx;

        const int rowlo = ylo * (FM_W * FM_C);   // float index of row start
        const int rowhi = yhi * (FM_W * FM_C);

        int4 off;
        off.x = rowlo + xlo * FM_C;   // (ylo, xlo)
        off.y = rowlo + xhi * FM_C;   // (ylo, xhi)
        off.z = rowhi + xlo * FM_C;   // (yhi, xlo)
        off.w = rowhi + xhi * FM_C;   // (yhi, xhi)
        s_off[px] = off;

        const float wy0 = 1.0f - ty, wy1 = ty;
        const float wx0 = 1.0f - tx, wx1 = tx;
        float4 w;
        w.x = wy0 * wx0;
        w.y = wy0 * wx1;
        w.z = wy1 * wx0;
        w.w = wy1 * wx1;
        s_w[px] = w;
    }
    __syncthreads();

    // Hoisted bases: every gather address is base_t + off (one IMAD.WIDE).
    const float* base_t = img + t;
    float*       optr   = out + (size_t)item * (POOL * FM_C) + t;

    #pragma unroll 2
    for (int px = 0; px < POOL; ++px) {
        const int4   off = s_off[px];   // broadcast LDS.128
        const float4 w   = s_w[px];     // broadcast LDS.128

        const float a  = __ldg(base_t + off.x);   // LDG.32: one 128B wavefront
        const float bq = __ldg(base_t + off.y);
        const float c  = __ldg(base_t + off.z);
        const float d  = __ldg(base_t + off.w);

        const float o = w.x * a + w.y * bq + w.z * c + w.w * d;

        __stcs(optr + px * FM_C, o);    // STG.32 [base + imm] after unroll
    }
}

extern "C" void kernel_launch(void* const* d_in, const int* in_sizes, int n_in,
                              void* d_out, int out_size)
{
    // Resolve inputs by size, not position: img = 5,120,000 elems; rois = 1,200.
    const float* img;
    const int*   rois;
    if (in_sizes[0] > in_sizes[1]) {
        img  = (const float*)d_in[0];
        rois = (const int*)d_in[1];
    } else {
        img  = (const float*)d_in[1];
        rois = (const int*)d_in[0];
    }
    float* out = (float*)d_out;

    roi_pool_kernel<<<NUM_ITEMS, 512>>>(img, rois, out);
}

// round 16
// speedup vs baseline: 1.1500x; 1.0516x over previous
#include <cuda_runtime.h>
#include <cuda_bf16.h>
#include <cstdint>

// ROI bilinear pooling (TF2 half_pixel_centers resize semantics).
// img: [1, 100, 100, 512] f32 NHWC ; rois: [1, 300, 4] int32 (x, y, w, h)
// out: [1, 300, 14, 14, 512] f32
//
// R15 (= R14 resubmit; prior run was a broker-level infra failure): move the
// OUTPUT stream off the L1tex pipe. Reads stay as R7's best measured form
// (8x LDG.64 per px, thread t owns float2 chunks t and t+128). Results are
// written to a 2-deep ring of 2KB smem px-buffers (STS = smem pipe), then
// copied smem->global via cp.async.bulk (async/TMA proxy -> LTS directly,
// zero L1tex wavefronts). Per warp-pixel L1 wavefronts drop from 20 (16 read
// + 4 store) to 16. Warp-scope pipeline only: each warp owns two 256B slices
// of the px buffer and elects lane 0 to issue its bulk copies -- no block
// barriers inside the px loop.

#define POOL 14
#define NUM_ROIS 300
#define FM_H 100
#define FM_W 100
#define FM_C 512
#define C2 (FM_C / 2)                 // 256 float2 per pixel row
#define NUM_ITEMS (NUM_ROIS * POOL)   // 4200
#define PX_BYTES (FM_C * 4)           // 2048 B per output pixel

__device__ __forceinline__ uint32_t smem_u32(const void* p) {
    uint32_t a;
    asm("{ .reg .u64 t; cvta.to.shared.u64 t, %1; cvt.u32.u64 %0, t; }"
        : "=r"(a) : "l"(p));
    return a;
}

__global__ __launch_bounds__(128, 8)
void roi_pool_kernel(const float2* __restrict__ img2,
                     const int*    __restrict__ rois,
                     float2*       __restrict__ out2)
{
    __shared__ int4   s_off[POOL];          // float2-elem offsets of 4 gather rows
    __shared__ float4 s_w[POOL];            // bilinear weights
    __shared__ __align__(16) float2 sbuf[2][2 * C2 / 2];  // 2 x 2KB px ring
    // sbuf[stage] holds 256 float2 = one full 512-channel pixel.

    const int t    = threadIdx.x;           // 0..127
    const int item = blockIdx.x;            // (roi, py)
    const int lane = t & 31;
    const int wid  = t >> 5;                // 0..3

    if (t < POOL) {
        const int px = t;
        const int r  = item / POOL;
        const int py = item - r * POOL;

        const int4 roi = __ldg(((const int4*)rois) + r);
        const int rx = roi.x, ry = roi.y, rw = roi.z, rh = roi.w;

        // y axis (half-pixel centers)
        const float srcy = (py + 0.5f) * ((float)rh * (1.0f / POOL)) - 0.5f;
        const float fy   = floorf(srcy);
        const float ty   = srcy - fy;
        const int   fyi  = (int)fy;
        const int   ylo  = min(max(fyi,     0), rh - 1) + ry;
        const int   yhi  = min(max(fyi + 1, 0), rh - 1) + ry;

        // x axis
        const float srcx = (px + 0.5f) * ((float)rw * (1.0f / POOL)) - 0.5f;
        const float fx   = floorf(srcx);
        const float tx   = srcx - fx;
        const int   fxi  = (int)fx;
        const int   xlo  = min(max(fxi,     0), rw - 1) + rx;
        const int   xhi  = min(max(fxi + 1, 0), rw - 1) + rx;

        const int rowlo = ylo * (FM_W * C2);
        const int rowhi = yhi * (FM_W * C2);

        int4 off;
        off.x = rowlo + xlo * C2;
        off.y = rowlo + xhi * C2;
        off.z = rowhi + xlo * C2;
        off.w = rowhi + xhi * C2;
        s_off[px] = off;

        const float wy0 = 1.0f - ty, wy1 = ty;
        const float wx0 = 1.0f - tx, wx1 = tx;
        float4 w;
        w.x = wy0 * wx0;
        w.y = wy0 * wx1;
        w.z = wy1 * wx0;
        w.w = wy1 * wx1;
        s_w[px] = w;
    }
    __syncthreads();

    // Byte base of this item's output block (28672 B per item).
    char* out_base = (char*)out2 + (size_t)item * (POOL * PX_BYTES);

    // Warp slice byte offsets within a px buffer: [256*wid, +256) and
    // [1024 + 256*wid, +256).
    const uint32_t sbuf_base0 = smem_u32(&sbuf[0][0]);
    const uint32_t sbuf_base1 = smem_u32(&sbuf[1][0]);
    const uint32_t slice_a = 256u * (uint32_t)wid;
    const uint32_t slice_b = 1024u + 256u * (uint32_t)wid;

    #pragma unroll
    for (int px = 0; px < POOL; ++px) {
        const int stage = px & 1;

        // Before overwriting this stage's buffer, drain the copy issued two
        // iterations ago (allow 1 group outstanding = px-1).
        if (px >= 2) {
            if (lane == 0)
                asm volatile("cp.async.bulk.wait_group 1;" ::: "memory");
            __syncwarp();
        }

        const int4   off = s_off[px];
        const float4 w   = s_w[px];

        const float2 a0 = __ldg(img2 + off.x + t);
        const float2 b0 = __ldg(img2 + off.y + t);
        const float2 c0 = __ldg(img2 + off.z + t);
        const float2 d0 = __ldg(img2 + off.w + t);
        const float2 a1 = __ldg(img2 + off.x + t + 128);
        const float2 b1 = __ldg(img2 + off.y + t + 128);
        const float2 c1 = __ldg(img2 + off.z + t + 128);
        const float2 d1 = __ldg(img2 + off.w + t + 128);

        float2 o0, o1;
        o0.x = w.x * a0.x + w.y * b0.x + w.z * c0.x + w.w * d0.x;
        o0.y = w.x * a0.y + w.y * b0.y + w.z * c0.y + w.w * d0.y;
        o1.x = w.x * a1.x + w.y * b1.x + w.z * c1.x + w.w * d1.x;
        o1.y = w.x * a1.y + w.y * b1.y + w.z * c1.y + w.w * d1.y;

        sbuf[stage][t]       = o0;     // STS.64, smem pipe
        sbuf[stage][t + 128] = o1;

        __syncwarp();
        if (lane == 0) {
            // Order this warp's STS before async-proxy reads.
            asm volatile("fence.proxy.async.shared::cta;" ::: "memory");
            const uint32_t sb = stage ? sbuf_base1 : sbuf_base0;
            char* gdst = out_base + px * PX_BYTES;
            asm volatile(
                "cp.async.bulk.global.shared::cta.bulk_group [%0], [%1], 256;"
                :: "l"(gdst + slice_a), "r"(sb + slice_a) : "memory");
            asm volatile(
                "cp.async.bulk.global.shared::cta.bulk_group [%0], [%1], 256;"
                :: "l"(gdst + slice_b), "r"(sb + slice_b) : "memory");
            asm volatile("cp.async.bulk.commit_group;" ::: "memory");
        }
        __syncwarp();
    }

    // Drain all outstanding copies before the block's smem is retired.
    if (lane == 0)
        asm volatile("cp.async.bulk.wait_group 0;" ::: "memory");
    __syncwarp();
}

extern "C" void kernel_launch(void* const* d_in, const int* in_sizes, int n_in,
                              void* d_out, int out_size)
{
    // Resolve inputs by size, not position: img = 5,120,000 elems; rois = 1,200.
    const float* img;
    const int*   rois;
    if (in_sizes[0] > in_sizes[1]) {
        img  = (const float*)d_in[0];
        rois = (const int*)d_in[1];
    } else {
        img  = (const float*)d_in[1];
        rois = (const int*)d_in[0];
    }
    float* out = (float*)d_out;

    roi_pool_kernel<<<NUM_ITEMS, 128>>>((const float2*)img, rois, (float2*)out);
}